// round 5
// baseline (speedup 1.0000x reference)
#include <cuda_runtime.h>
#include <cuda_bf16.h>
#include <math.h>

#define BSZ 2
#define SEQ 2048
#define DIM 1024
#define NH  16
#define HD  64
#define NTOK (BSZ*SEQ)            // 4096
#define NELEM ((size_t)NTOK*DIM)  // 4,194,304
#define WELEM ((size_t)DIM*DIM)   // 1,048,576

// Scratch (allocation-free rule: __device__ globals)
__device__ float g_M[NELEM];               // merged attention output [B,S,H*HD]
__device__ float g_qr[NELEM], g_kr[NELEM], g_vr[NELEM];   // tf32-rounded inputs
__device__ float g_Wr[4][WELEM];                           // tf32-rounded Wq,Wk,Wv,Wo
__device__ __nv_bfloat16 g_Qh[NELEM], g_Ql[NELEM];
__device__ __nv_bfloat16 g_Kh[NELEM], g_Kl[NELEM];
__device__ __nv_bfloat16 g_Vh[NELEM], g_Vl[NELEM];

// ---------------------------------------------------------------------------
// small PTX helpers
// ---------------------------------------------------------------------------
__device__ __forceinline__ unsigned f2tf32(float f) {
    unsigned r;
    asm("cvt.rna.tf32.f32 %0, %1;" : "=r"(r) : "f"(f));
    return r;
}
__device__ __forceinline__ unsigned packbf2(float hi, float lo) {
    unsigned d;
    asm("cvt.rn.bf16x2.f32 %0, %1, %2;" : "=r"(d) : "f"(hi), "f"(lo));
    return d;
}
__device__ __forceinline__ void cp_async16(unsigned smem_addr, const void* gptr) {
    asm volatile("cp.async.cg.shared.global [%0], [%1], 16;\n"
                 :: "r"(smem_addr), "l"(gptr));
}
__device__ __forceinline__ void cp_commit() {
    asm volatile("cp.async.commit_group;\n");
}
template <int N>
__device__ __forceinline__ void cp_wait() {
    asm volatile("cp.async.wait_group %0;\n" :: "n"(N));
}
__device__ __forceinline__ void ldsm_x4(unsigned* r, unsigned addr) {
    asm volatile("ldmatrix.sync.aligned.m8n8.x4.shared.b16 {%0,%1,%2,%3}, [%4];"
                 : "=r"(r[0]), "=r"(r[1]), "=r"(r[2]), "=r"(r[3]) : "r"(addr));
}
__device__ __forceinline__ void ldsm_x4_t(unsigned* r, unsigned addr) {
    asm volatile("ldmatrix.sync.aligned.m8n8.x4.trans.shared.b16 {%0,%1,%2,%3}, [%4];"
                 : "=r"(r[0]), "=r"(r[1]), "=r"(r[2]), "=r"(r[3]) : "r"(addr));
}
__device__ __forceinline__ void mma_bf16(float* c, const unsigned* a,
                                         unsigned b0, unsigned b1) {
    asm volatile(
        "mma.sync.aligned.m16n8k16.row.col.f32.bf16.bf16.f32 "
        "{%0,%1,%2,%3},{%4,%5,%6,%7},{%8,%9},{%0,%1,%2,%3};"
        : "+f"(c[0]), "+f"(c[1]), "+f"(c[2]), "+f"(c[3])
        : "r"(a[0]), "r"(a[1]), "r"(a[2]), "r"(a[3]), "r"(b0), "r"(b1));
}

// ---------------------------------------------------------------------------
// Pre-round fp32 -> tf32 grid (RNA). Makes the GEMM inner loop cvt-free:
// HW truncation of already-rounded values is exact.
// ---------------------------------------------------------------------------
__global__ void __launch_bounds__(256)
preround(const float* __restrict__ src, float* __restrict__ dst, int n4)
{
    int i = blockIdx.x * blockDim.x + threadIdx.x;
    if (i < n4) {
        float4 v = ((const float4*)src)[i];
        v.x = __uint_as_float(f2tf32(v.x));
        v.y = __uint_as_float(f2tf32(v.y));
        v.z = __uint_as_float(f2tf32(v.z));
        v.w = __uint_as_float(f2tf32(v.w));
        ((float4*)dst)[i] = v;
    }
}

// ---------------------------------------------------------------------------
// TF32 tensor-core GEMM; operands MUST be pre-rounded to the tf32 grid.
// Inner loop is pure LDS + MMA (no cvt). Epilogue optionally emits bf16
// hi/lo planes (for Q/K/V) instead of fp32.
// ---------------------------------------------------------------------------
#define GBM 128
#define GBN 128
#define GBK 32
#define ASTRIDE 36
#define BSTRIDE 136
#define STAGE_FLOATS (GBM*ASTRIDE + GBK*BSTRIDE)

__global__ void __launch_bounds__(256, 2)
gemm_tf32(const float* __restrict__ A, const float* __restrict__ B,
          float* __restrict__ Cf,
          __nv_bfloat16* __restrict__ Ch, __nv_bfloat16* __restrict__ Cl,
          float scale, int M, int N, int K)
{
    extern __shared__ float sm[];
    const int tid  = threadIdx.x;
    const int lane = tid & 31;
    const int warp = tid >> 5;
    const int wm   = warp >> 2;
    const int wn   = warp & 3;

    const int bRow = blockIdx.y;
    const int bCol = blockIdx.x;

    const float* Ab = A + (size_t)bRow * GBM * K;
    const float* Bb = B + (size_t)bCol * GBN;

    unsigned smem_base;
    asm("{ .reg .u64 t; cvta.to.shared.u64 t, %1; cvt.u32.u64 %0, t; }"
        : "=r"(smem_base) : "l"(sm));

    const int aRowL = tid >> 3;
    const int aColL = (tid & 7) * 4;
    const int bRowL = tid >> 5;
    const int bColL = (tid & 31) * 4;

    float c[4][4][4];
    #pragma unroll
    for (int mt = 0; mt < 4; mt++)
        #pragma unroll
        for (int nt = 0; nt < 4; nt++)
            #pragma unroll
            for (int e = 0; e < 4; e++) c[mt][nt][e] = 0.0f;

    const int niter = K / GBK;

    auto load_stage = [&](int iter, int buf) {
        const int k0 = iter * GBK;
        unsigned aBase = smem_base + (unsigned)(buf * STAGE_FLOATS) * 4u;
        unsigned bBase = aBase + GBM * ASTRIDE * 4u;
        #pragma unroll
        for (int it = 0; it < 4; it++) {
            int r = aRowL + it * 32;
            cp_async16(aBase + (r * ASTRIDE + aColL) * 4u,
                       Ab + (size_t)r * K + k0 + aColL);
        }
        #pragma unroll
        for (int it = 0; it < 4; it++) {
            int r = bRowL + it * 8;
            cp_async16(bBase + (r * BSTRIDE + bColL) * 4u,
                       Bb + (size_t)(k0 + r) * N + bColL);
        }
    };

    load_stage(0, 0); cp_commit();
    load_stage(1, 1); cp_commit();

    const int g  = lane >> 2;
    const int tg = lane & 3;

    for (int i = 0; i < niter; i++) {
        cp_wait<1>();
        __syncthreads();

        const int buf = i & 1;
        const float* As = sm + buf * STAGE_FLOATS;
        const float* Bs = As + GBM * ASTRIDE;

        #pragma unroll
        for (int kk = 0; kk < GBK / 8; kk++) {
            unsigned af[4][4], bf[4][2];
            const int c0 = kk * 8 + tg;
            #pragma unroll
            for (int mt = 0; mt < 4; mt++) {
                int r0 = wm * 64 + mt * 16 + g;
                af[mt][0] = __float_as_uint(As[r0       * ASTRIDE + c0]);
                af[mt][1] = __float_as_uint(As[(r0 + 8) * ASTRIDE + c0]);
                af[mt][2] = __float_as_uint(As[r0       * ASTRIDE + c0 + 4]);
                af[mt][3] = __float_as_uint(As[(r0 + 8) * ASTRIDE + c0 + 4]);
            }
            #pragma unroll
            for (int nt = 0; nt < 4; nt++) {
                int col = wn * 32 + nt * 8 + g;
                bf[nt][0] = __float_as_uint(Bs[c0       * BSTRIDE + col]);
                bf[nt][1] = __float_as_uint(Bs[(c0 + 4) * BSTRIDE + col]);
            }
            #pragma unroll
            for (int mt = 0; mt < 4; mt++)
                #pragma unroll
                for (int nt = 0; nt < 4; nt++) {
                    asm volatile(
                        "mma.sync.aligned.m16n8k8.row.col.f32.tf32.tf32.f32 "
                        "{%0,%1,%2,%3},{%4,%5,%6,%7},{%8,%9},{%0,%1,%2,%3};\n"
                        : "+f"(c[mt][nt][0]), "+f"(c[mt][nt][1]),
                          "+f"(c[mt][nt][2]), "+f"(c[mt][nt][3])
                        : "r"(af[mt][0]), "r"(af[mt][1]),
                          "r"(af[mt][2]), "r"(af[mt][3]),
                          "r"(bf[nt][0]), "r"(bf[nt][1]));
                }
        }
        __syncthreads();
        if (i + 2 < niter) load_stage(i + 2, buf);
        cp_commit();
    }

    // Epilogue
    if (Ch) {
        #pragma unroll
        for (int mt = 0; mt < 4; mt++) {
            int r0 = bRow * GBM + wm * 64 + mt * 16 + g;
            #pragma unroll
            for (int nt = 0; nt < 4; nt++) {
                int col = bCol * GBN + wn * 32 + nt * 8 + 2 * tg;
                #pragma unroll
                for (int half = 0; half < 2; half++) {
                    size_t off = (size_t)(r0 + 8 * half) * N + col;
                    float y0 = c[mt][nt][2 * half + 0] * scale;
                    float y1 = c[mt][nt][2 * half + 1] * scale;
                    unsigned hi = packbf2(y1, y0);
                    float h0 = __uint_as_float(hi << 16);
                    float h1 = __uint_as_float(hi & 0xffff0000u);
                    unsigned lo = packbf2(y1 - h1, y0 - h0);
                    *(unsigned*)((__nv_bfloat16*)Ch + off) = hi;
                    *(unsigned*)((__nv_bfloat16*)Cl + off) = lo;
                }
            }
        }
    } else {
        float* Cb = Cf + (size_t)bRow * GBM * N + bCol * GBN;
        #pragma unroll
        for (int mt = 0; mt < 4; mt++) {
            int r0 = wm * 64 + mt * 16 + g;
            #pragma unroll
            for (int nt = 0; nt < 4; nt++) {
                int col = wn * 32 + nt * 8 + 2 * tg;
                *(float2*)(Cb + (size_t)r0 * N + col) =
                    make_float2(c[mt][nt][0], c[mt][nt][1]);
                *(float2*)(Cb + (size_t)(r0 + 8) * N + col) =
                    make_float2(c[mt][nt][2], c[mt][nt][3]);
            }
        }
    }
}

// ---------------------------------------------------------------------------
// Flash attention, bf16 tensor cores, 3-term hi/lo split, cp.async
// double-buffered K/V tiles. merged[] is written tf32-RNA-rounded so the
// final GEMM can consume it cvt-free; attn_out keeps full fp32.
// ---------------------------------------------------------------------------
#define RS 72
#define KVSTAGE (4*64*RS)
#define SQH 0
#define SQL (128*RS)
#define SB_TOTAL (2*KVSTAGE)           // 36864 bf16 = 73728 B
#define OKH 0
#define OKL (64*RS)
#define OVH (128*RS)
#define OVL (192*RS)

__global__ void __launch_bounds__(256, 1)
flash_bf16(const __nv_bfloat16* __restrict__ Qh, const __nv_bfloat16* __restrict__ Ql,
           const __nv_bfloat16* __restrict__ Kh, const __nv_bfloat16* __restrict__ Kl,
           const __nv_bfloat16* __restrict__ Vh, const __nv_bfloat16* __restrict__ Vl,
           float* __restrict__ merged, float* __restrict__ attn_out,
           int write_attn, const int* __restrict__ maskedp)
{
    extern __shared__ __nv_bfloat16 sb[];
    const int qt  = gridDim.x - 1 - blockIdx.x;
    const int h   = blockIdx.y;
    const int b   = blockIdx.z;
    const int tid = threadIdx.x;
    const int lane = tid & 31;
    const int w   = tid >> 5;
    const int q0  = qt * 128;
    const int masked = maskedp[0];

    unsigned sbase;
    asm("{ .reg .u64 t; cvta.to.shared.u64 t, %1; cvt.u32.u64 %0, t; }"
        : "=r"(sbase) : "l"(sb));

    const int ktmax = masked ? (2 * qt + 1) : (SEQ / 64 - 1);

    auto stage_off = [](int kt) -> unsigned { return (kt & 1) ? 0u : (unsigned)KVSTAGE; };

    auto prefetch = [&](int t) {
        if (t <= ktmax) {
            unsigned so = stage_off(t);
            int r  = tid >> 3;
            int c8 = (tid & 7) << 3;
            #pragma unroll
            for (int half = 0; half < 2; half++) {
                int rr = r + 32 * half;
                size_t gidx = ((size_t)(b * SEQ + t * 64 + rr) * DIM) + h * HD + c8;
                unsigned sa = sbase + (so + rr * RS + c8) * 2;
                cp_async16(sa + OKH * 2, Kh + gidx);
                cp_async16(sa + OKL * 2, Kl + gidx);
                cp_async16(sa + OVH * 2, Vh + gidx);
                cp_async16(sa + OVL * 2, Vl + gidx);
            }
        }
        cp_commit();
    };

    prefetch(0);
    for (int i = tid; i < 1024; i += 256) {
        int r = i >> 3, c8 = (i & 7) << 3;
        size_t gidx = ((size_t)(b * SEQ + q0 + r) * DIM) + h * HD + c8;
        *(uint4*)(sb + SQH + r * RS + c8) = *(const uint4*)(Qh + gidx);
        *(uint4*)(sb + SQL + r * RS + c8) = *(const uint4*)(Ql + gidx);
    }
    __syncthreads();

    unsigned qf[2][4][4];
    {
        int row  = 16 * w + (lane & 15);
        int coct = (lane >> 4) << 3;
        #pragma unroll
        for (int p = 0; p < 2; p++)
            #pragma unroll
            for (int d = 0; d < 4; d++) {
                unsigned addr = sbase +
                    ((p ? SQL : SQH) + row * RS + d * 16 + coct) * 2;
                ldsm_x4(qf[p][d], addr);
            }
    }
    __syncthreads();
    prefetch(1);

    float o[8][4];
    #pragma unroll
    for (int j = 0; j < 8; j++)
        #pragma unroll
        for (int e = 0; e < 4; e++) o[j][e] = 0.0f;
    float m0 = -1e30f, m1 = -1e30f, l0 = 0.0f, l1 = 0.0f;

    const int r_lo = q0 + 16 * w + (lane >> 2);
    const int r_hi = r_lo + 8;

    for (int kt = 0; kt <= ktmax; kt++) {
        cp_wait<1>();
        __syncthreads();

        const unsigned so = stage_off(kt);
        const int k0 = kt * 64;
        const bool active = !(masked && k0 > q0 + 16 * w + 15);

        if (active) {
            float s[8][4];
            #pragma unroll
            for (int j = 0; j < 8; j++)
                #pragma unroll
                for (int e = 0; e < 4; e++) s[j][e] = 0.0f;

            #pragma unroll
            for (int j = 0; j < 8; j++) {
                unsigned kbh[8], kbl[8];
                int krow = 8 * j + (lane & 7);
                int dct  = (lane >> 3) << 3;
                ldsm_x4(&kbh[0], sbase + (so + OKH + krow * RS + dct) * 2);
                ldsm_x4(&kbh[4], sbase + (so + OKH + krow * RS + 32 + dct) * 2);
                ldsm_x4(&kbl[0], sbase + (so + OKL + krow * RS + dct) * 2);
                ldsm_x4(&kbl[4], sbase + (so + OKL + krow * RS + 32 + dct) * 2);
                #pragma unroll
                for (int d = 0; d < 4; d++) {
                    mma_bf16(s[j], qf[0][d], kbh[2*d], kbh[2*d+1]);
                    mma_bf16(s[j], qf[0][d], kbl[2*d], kbl[2*d+1]);
                    mma_bf16(s[j], qf[1][d], kbh[2*d], kbh[2*d+1]);
                }
            }

            if (masked && k0 + 63 > r_lo) {
                #pragma unroll
                for (int j = 0; j < 8; j++) {
                    int cc = k0 + 8 * j + 2 * (lane & 3);
                    if (cc     > r_lo) s[j][0] = -1e30f;
                    if (cc + 1 > r_lo) s[j][1] = -1e30f;
                    if (cc     > r_hi) s[j][2] = -1e30f;
                    if (cc + 1 > r_hi) s[j][3] = -1e30f;
                }
            }

            float mt0 = -1e30f, mt1 = -1e30f;
            #pragma unroll
            for (int j = 0; j < 8; j++) {
                mt0 = fmaxf(mt0, fmaxf(s[j][0], s[j][1]));
                mt1 = fmaxf(mt1, fmaxf(s[j][2], s[j][3]));
            }
            mt0 = fmaxf(mt0, __shfl_xor_sync(0xffffffffu, mt0, 1));
            mt0 = fmaxf(mt0, __shfl_xor_sync(0xffffffffu, mt0, 2));
            mt1 = fmaxf(mt1, __shfl_xor_sync(0xffffffffu, mt1, 1));
            mt1 = fmaxf(mt1, __shfl_xor_sync(0xffffffffu, mt1, 2));
            float mn0 = fmaxf(m0, mt0), mn1 = fmaxf(m1, mt1);
            float a0 = __expf(m0 - mn0), a1 = __expf(m1 - mn1);
            m0 = mn0; m1 = mn1;

            float rs0 = 0.0f, rs1 = 0.0f;
            unsigned pah[4][4], pal[4][4];
            #pragma unroll
            for (int j = 0; j < 8; j++) {
                float p0 = __expf(s[j][0] - mn0);
                float p1 = __expf(s[j][1] - mn0);
                float p2 = __expf(s[j][2] - mn1);
                float p3 = __expf(s[j][3] - mn1);
                rs0 += p0 + p1; rs1 += p2 + p3;
                unsigned h01 = packbf2(p1, p0);
                unsigned h23 = packbf2(p3, p2);
                float q0f = __uint_as_float(h01 << 16);
                float q1f = __uint_as_float(h01 & 0xffff0000u);
                float q2f = __uint_as_float(h23 << 16);
                float q3f = __uint_as_float(h23 & 0xffff0000u);
                unsigned lo01 = packbf2(p1 - q1f, p0 - q0f);
                unsigned lo23 = packbf2(p3 - q3f, p2 - q2f);
                int t = j >> 1, half = j & 1;
                pah[t][2 * half + 0] = h01;
                pah[t][2 * half + 1] = h23;
                pal[t][2 * half + 0] = lo01;
                pal[t][2 * half + 1] = lo23;
            }
            rs0 += __shfl_xor_sync(0xffffffffu, rs0, 1);
            rs0 += __shfl_xor_sync(0xffffffffu, rs0, 2);
            rs1 += __shfl_xor_sync(0xffffffffu, rs1, 1);
            rs1 += __shfl_xor_sync(0xffffffffu, rs1, 2);
            l0 = l0 * a0 + rs0;
            l1 = l1 * a1 + rs1;
            #pragma unroll
            for (int j = 0; j < 8; j++) {
                o[j][0] *= a0; o[j][1] *= a0;
                o[j][2] *= a1; o[j][3] *= a1;
            }

            #pragma unroll
            for (int jn = 0; jn < 8; jn++) {
                unsigned vbh[8], vbl[8];
                ldsm_x4_t(&vbh[0], sbase + (so + OVH + lane * RS + 8 * jn) * 2);
                ldsm_x4_t(&vbh[4], sbase + (so + OVH + (32 + lane) * RS + 8 * jn) * 2);
                ldsm_x4_t(&vbl[0], sbase + (so + OVL + lane * RS + 8 * jn) * 2);
                ldsm_x4_t(&vbl[4], sbase + (so + OVL + (32 + lane) * RS + 8 * jn) * 2);
                #pragma unroll
                for (int t = 0; t < 4; t++) {
                    mma_bf16(o[jn], pah[t], vbh[2*t], vbh[2*t+1]);
                    mma_bf16(o[jn], pah[t], vbl[2*t], vbl[2*t+1]);
                    mma_bf16(o[jn], pal[t], vbh[2*t], vbh[2*t+1]);
                }
            }
        }

        __syncthreads();
        prefetch(kt + 2);
    }

    // finalize + write (merged gets tf32-RNA rounding; attn_out full fp32)
    float il0 = 1.0f / l0, il1 = 1.0f / l1;
    #pragma unroll
    for (int jn = 0; jn < 8; jn++) {
        int col = 8 * jn + 2 * (lane & 3);
        float f00 = o[jn][0] * il0, f01 = o[jn][1] * il0;
        float f10 = o[jn][2] * il1, f11 = o[jn][3] * il1;
        float2 m0v = make_float2(__uint_as_float(f2tf32(f00)),
                                 __uint_as_float(f2tf32(f01)));
        float2 m1v = make_float2(__uint_as_float(f2tf32(f10)),
                                 __uint_as_float(f2tf32(f11)));
        *(float2*)(merged + ((size_t)(b * SEQ + r_lo) * DIM) + h * HD + col) = m0v;
        *(float2*)(merged + ((size_t)(b * SEQ + r_hi) * DIM) + h * HD + col) = m1v;
        if (write_attn) {
            *(float2*)(attn_out + (((size_t)(b * NH + h) * SEQ + r_lo) * HD) + col) =
                make_float2(f00, f01);
            *(float2*)(attn_out + (((size_t)(b * NH + h) * SEQ + r_hi) * HD) + col) =
                make_float2(f10, f11);
        }
    }
}

// ---------------------------------------------------------------------------
extern "C" void kernel_launch(void* const* d_in, const int* in_sizes, int n_in,
                              void* d_out, int out_size)
{
    const float* q  = (const float*)d_in[0];
    const float* k  = (const float*)d_in[1];
    const float* v  = (const float*)d_in[2];
    const float* Wq = (const float*)d_in[3];
    const float* Wk = (const float*)d_in[4];
    const float* Wv = (const float*)d_in[5];
    const float* Wo = (const float*)d_in[6];
    const int* masked = (const int*)d_in[7];
    float* out = (float*)d_out;

    float *pM, *pqr, *pkr, *pvr, *pWr;
    __nv_bfloat16 *pQh, *pQl, *pKh, *pKl, *pVh, *pVl;
    cudaGetSymbolAddress((void**)&pM,  g_M);
    cudaGetSymbolAddress((void**)&pqr, g_qr);
    cudaGetSymbolAddress((void**)&pkr, g_kr);
    cudaGetSymbolAddress((void**)&pvr, g_vr);
    cudaGetSymbolAddress((void**)&pWr, g_Wr);
    cudaGetSymbolAddress((void**)&pQh, g_Qh);
    cudaGetSymbolAddress((void**)&pQl, g_Ql);
    cudaGetSymbolAddress((void**)&pKh, g_Kh);
    cudaGetSymbolAddress((void**)&pKl, g_Kl);
    cudaGetSymbolAddress((void**)&pVh, g_Vh);
    cudaGetSymbolAddress((void**)&pVl, g_Vl);

    // Pre-round all GEMM operands to the tf32 grid (RNA, idempotent).
    {
        int n4t = (int)(NELEM / 4);
        int n4w = (int)(WELEM / 4);
        preround<<<(n4t + 255) / 256, 256>>>(q, pqr, n4t);
        preround<<<(n4t + 255) / 256, 256>>>(k, pkr, n4t);
        preround<<<(n4t + 255) / 256, 256>>>(v, pvr, n4t);
        preround<<<(n4w + 255) / 256, 256>>>(Wq, pWr + 0 * WELEM, n4w);
        preround<<<(n4w + 255) / 256, 256>>>(Wk, pWr + 1 * WELEM, n4w);
        preround<<<(n4w + 255) / 256, 256>>>(Wv, pWr + 2 * WELEM, n4w);
        preround<<<(n4w + 255) / 256, 256>>>(Wo, pWr + 3 * WELEM, n4w);
    }

    dim3 gGemm(DIM / GBN, NTOK / GBM);
    size_t gemm_smem = 2 * STAGE_FLOATS * sizeof(float);
    cudaFuncSetAttribute(gemm_tf32, cudaFuncAttributeMaxDynamicSharedMemorySize,
                         (int)gemm_smem);

    // Projections -> bf16 hi/lo planes (Q pre-scaled by 1/sqrt(hd))
    gemm_tf32<<<gGemm, 256, gemm_smem>>>(pqr, pWr + 0 * WELEM, nullptr, pQh, pQl,
                                         0.125f, NTOK, DIM, DIM);
    gemm_tf32<<<gGemm, 256, gemm_smem>>>(pkr, pWr + 1 * WELEM, nullptr, pKh, pKl,
                                         1.0f, NTOK, DIM, DIM);
    gemm_tf32<<<gGemm, 256, gemm_smem>>>(pvr, pWr + 2 * WELEM, nullptr, pVh, pVl,
                                         1.0f, NTOK, DIM, DIM);

    // Attention
    int write_attn = (out_size >= (int)(2 * NELEM)) ? 1 : 0;
    float* attn_ptr = out + NELEM;
    size_t fl_smem = (size_t)SB_TOTAL * sizeof(__nv_bfloat16);
    cudaFuncSetAttribute(flash_bf16, cudaFuncAttributeMaxDynamicSharedMemorySize,
                         (int)fl_smem);
    dim3 gAttn(SEQ / 128, NH, BSZ);
    flash_bf16<<<gAttn, 256, fl_smem>>>(pQh, pQl, pKh, pKl, pVh, pVl,
                                        pM, attn_ptr, write_attn, masked);

    // Output projection (merged already tf32-rounded by flash epilogue)
    gemm_tf32<<<gGemm, 256, gemm_smem>>>(pM, pWr + 3 * WELEM, out, nullptr, nullptr,
                                         1.0f, NTOK, DIM, DIM);
}

// round 6
// speedup vs baseline: 1.0066x; 1.0066x over previous
#include <cuda_runtime.h>
#include <cuda_bf16.h>
#include <math.h>

#define BSZ 2
#define SEQ 2048
#define DIM 1024
#define NH  16
#define HD  64
#define NTOK (BSZ*SEQ)            // 4096
#define NELEM ((size_t)NTOK*DIM)  // 4,194,304

// Scratch (allocation-free rule: __device__ globals)
__device__ float g_M[NELEM];               // merged attention output [B,S,H*HD]
__device__ __nv_bfloat16 g_Qh[NELEM], g_Ql[NELEM];
__device__ __nv_bfloat16 g_Kh[NELEM], g_Kl[NELEM];
__device__ __nv_bfloat16 g_Vh[NELEM], g_Vl[NELEM];

// ---------------------------------------------------------------------------
// small PTX helpers
// ---------------------------------------------------------------------------
__device__ __forceinline__ unsigned f2tf32(float f) {
    unsigned r;
    asm("cvt.rna.tf32.f32 %0, %1;" : "=r"(r) : "f"(f));
    return r;
}
__device__ __forceinline__ unsigned packbf2(float hi, float lo) {
    unsigned d;
    asm("cvt.rn.bf16x2.f32 %0, %1, %2;" : "=r"(d) : "f"(hi), "f"(lo));
    return d;
}
__device__ __forceinline__ void cp_async16(unsigned smem_addr, const void* gptr) {
    asm volatile("cp.async.cg.shared.global [%0], [%1], 16;\n"
                 :: "r"(smem_addr), "l"(gptr));
}
__device__ __forceinline__ void cp_commit() {
    asm volatile("cp.async.commit_group;\n");
}
template <int N>
__device__ __forceinline__ void cp_wait() {
    asm volatile("cp.async.wait_group %0;\n" :: "n"(N));
}
__device__ __forceinline__ void ldsm_x4(unsigned* r, unsigned addr) {
    asm volatile("ldmatrix.sync.aligned.m8n8.x4.shared.b16 {%0,%1,%2,%3}, [%4];"
                 : "=r"(r[0]), "=r"(r[1]), "=r"(r[2]), "=r"(r[3]) : "r"(addr));
}
__device__ __forceinline__ void ldsm_x4_t(unsigned* r, unsigned addr) {
    asm volatile("ldmatrix.sync.aligned.m8n8.x4.trans.shared.b16 {%0,%1,%2,%3}, [%4];"
                 : "=r"(r[0]), "=r"(r[1]), "=r"(r[2]), "=r"(r[3]) : "r"(addr));
}
__device__ __forceinline__ void mma_bf16(float* c, const unsigned* a,
                                         unsigned b0, unsigned b1) {
    asm volatile(
        "mma.sync.aligned.m16n8k16.row.col.f32.bf16.bf16.f32 "
        "{%0,%1,%2,%3},{%4,%5,%6,%7},{%8,%9},{%0,%1,%2,%3};"
        : "+f"(c[0]), "+f"(c[1]), "+f"(c[2]), "+f"(c[3])
        : "r"(a[0]), "r"(a[1]), "r"(a[2]), "r"(a[3]), "r"(b0), "r"(b1));
}

// ---------------------------------------------------------------------------
// TF32 GEMM core: C[M,N] += A[M,K] @ B[K,N], 128x128 block, GBK=16,
// 4-stage cp.async pipeline, single __syncthreads per iteration, prefetch
// issued BEFORE compute. 8 warps, 64x32 warp tile, in-loop tf32 cvt.
// ---------------------------------------------------------------------------
#define GBM 128
#define GBN 128
#define GBK 16
#define ASTRIDE 20    // GBK+4: A-frag banks 20g+tg mod 32 all distinct
#define BSTRIDE 136   // GBN+8: B-frag banks 8tg+g mod 32 all distinct
#define STAGE_FLOATS (GBM*ASTRIDE + GBK*BSTRIDE)   // 2560+2176 = 4736
#define NSTAGE 4
#define GEMM_SMEM (NSTAGE*STAGE_FLOATS*4)          // 75776 B

__device__ __forceinline__ void gemm_core(
    const float* __restrict__ A, const float* __restrict__ B,
    float* __restrict__ Cf,
    __nv_bfloat16* __restrict__ Ch, __nv_bfloat16* __restrict__ Cl,
    float scale, int M, int N, int K, float* sm)
{
    const int tid  = threadIdx.x;
    const int lane = tid & 31;
    const int warp = tid >> 5;
    const int wm   = warp >> 2;          // 0..1
    const int wn   = warp & 3;           // 0..3

    const int bRow = blockIdx.y;
    const int bCol = blockIdx.x;

    const float* Ab = A + (size_t)bRow * GBM * K;
    const float* Bb = B + (size_t)bCol * GBN;

    unsigned smem_base;
    asm("{ .reg .u64 t; cvta.to.shared.u64 t, %1; cvt.u32.u64 %0, t; }"
        : "=r"(smem_base) : "l"(sm));

    float c[4][4][4];
    #pragma unroll
    for (int mt = 0; mt < 4; mt++)
        #pragma unroll
        for (int nt = 0; nt < 4; nt++)
            #pragma unroll
            for (int e = 0; e < 4; e++) c[mt][nt][e] = 0.0f;

    const int niter = K / GBK;           // 64

    auto load_stage = [&](int iter, int buf) {
        const int k0 = iter * GBK;
        unsigned aBase = smem_base + (unsigned)(buf * STAGE_FLOATS) * 4u;
        unsigned bBase = aBase + GBM * ASTRIDE * 4u;
        // A: 128 rows x 16 k  (2 x float4 per thread)
        #pragma unroll
        for (int it = 0; it < 2; it++) {
            int r  = (tid >> 2) + 64 * it;
            int c4 = (tid & 3) * 4;
            cp_async16(aBase + (r * ASTRIDE + c4) * 4u,
                       Ab + (size_t)r * K + k0 + c4);
        }
        // B: 16 rows x 128 n  (2 x float4 per thread)
        #pragma unroll
        for (int it = 0; it < 2; it++) {
            int idx = tid + 256 * it;
            int r   = idx >> 5;
            int c4  = (idx & 31) * 4;
            cp_async16(bBase + (r * BSTRIDE + c4) * 4u,
                       Bb + (size_t)(k0 + r) * N + c4);
        }
    };

    // prologue: 3 stages in flight
    load_stage(0, 0); cp_commit();
    load_stage(1, 1); cp_commit();
    load_stage(2, 2); cp_commit();

    const int g  = lane >> 2;
    const int tg = lane & 3;

    for (int i = 0; i < niter; i++) {
        cp_wait<2>();            // stage i arrived
        __syncthreads();         // also separates iter i-1 reads from refill

        // prefetch i+3 into the buffer consumed at iter i-1 (safe: all warps
        // passed the barrier above). Issued BEFORE compute for full overlap.
        if (i + 3 < niter) load_stage(i + 3, (i + 3) & 3);
        cp_commit();

        const int buf = i & 3;
        const float* As = sm + buf * STAGE_FLOATS;
        const float* Bs = As + GBM * ASTRIDE;

        #pragma unroll
        for (int kk = 0; kk < GBK / 8; kk++) {
            unsigned af[4][4], bf[4][2];
            const int c0 = kk * 8 + tg;
            #pragma unroll
            for (int mt = 0; mt < 4; mt++) {
                int r0 = wm * 64 + mt * 16 + g;
                af[mt][0] = f2tf32(As[r0       * ASTRIDE + c0]);
                af[mt][1] = f2tf32(As[(r0 + 8) * ASTRIDE + c0]);
                af[mt][2] = f2tf32(As[r0       * ASTRIDE + c0 + 4]);
                af[mt][3] = f2tf32(As[(r0 + 8) * ASTRIDE + c0 + 4]);
            }
            #pragma unroll
            for (int nt = 0; nt < 4; nt++) {
                int col = wn * 32 + nt * 8 + g;
                bf[nt][0] = f2tf32(Bs[c0       * BSTRIDE + col]);
                bf[nt][1] = f2tf32(Bs[(c0 + 4) * BSTRIDE + col]);
            }
            #pragma unroll
            for (int mt = 0; mt < 4; mt++)
                #pragma unroll
                for (int nt = 0; nt < 4; nt++) {
                    asm volatile(
                        "mma.sync.aligned.m16n8k8.row.col.f32.tf32.tf32.f32 "
                        "{%0,%1,%2,%3},{%4,%5,%6,%7},{%8,%9},{%0,%1,%2,%3};\n"
                        : "+f"(c[mt][nt][0]), "+f"(c[mt][nt][1]),
                          "+f"(c[mt][nt][2]), "+f"(c[mt][nt][3])
                        : "r"(af[mt][0]), "r"(af[mt][1]),
                          "r"(af[mt][2]), "r"(af[mt][3]),
                          "r"(bf[nt][0]), "r"(bf[nt][1]));
                }
        }
    }

    // Epilogue
    if (Ch) {
        #pragma unroll
        for (int mt = 0; mt < 4; mt++) {
            int r0 = bRow * GBM + wm * 64 + mt * 16 + g;
            #pragma unroll
            for (int nt = 0; nt < 4; nt++) {
                int col = bCol * GBN + wn * 32 + nt * 8 + 2 * tg;
                #pragma unroll
                for (int half = 0; half < 2; half++) {
                    size_t off = (size_t)(r0 + 8 * half) * N + col;
                    float y0 = c[mt][nt][2 * half + 0] * scale;
                    float y1 = c[mt][nt][2 * half + 1] * scale;
                    unsigned hi = packbf2(y1, y0);
                    float h0 = __uint_as_float(hi << 16);
                    float h1 = __uint_as_float(hi & 0xffff0000u);
                    unsigned lo = packbf2(y1 - h1, y0 - h0);
                    *(unsigned*)(Ch + off) = hi;
                    *(unsigned*)(Cl + off) = lo;
                }
            }
        }
    } else {
        float* Cb = Cf + (size_t)bRow * GBM * N + bCol * GBN;
        #pragma unroll
        for (int mt = 0; mt < 4; mt++) {
            int r0 = wm * 64 + mt * 16 + g;
            #pragma unroll
            for (int nt = 0; nt < 4; nt++) {
                int col = wn * 32 + nt * 8 + 2 * tg;
                *(float2*)(Cb + (size_t)r0 * N + col) =
                    make_float2(c[mt][nt][0], c[mt][nt][1]);
                *(float2*)(Cb + (size_t)(r0 + 8) * N + col) =
                    make_float2(c[mt][nt][2], c[mt][nt][3]);
            }
        }
    }
}

// Fused Q/K/V projections: grid.z selects which GEMM this CTA works on.
__global__ void __launch_bounds__(256, 2)
qkv_gemm(const float* __restrict__ q, const float* __restrict__ k,
         const float* __restrict__ v,
         const float* __restrict__ Wq, const float* __restrict__ Wk,
         const float* __restrict__ Wv,
         __nv_bfloat16* Qh, __nv_bfloat16* Ql,
         __nv_bfloat16* Kh, __nv_bfloat16* Kl,
         __nv_bfloat16* Vh, __nv_bfloat16* Vl)
{
    extern __shared__ float sm[];
    const int z = blockIdx.z;
    const float* A = (z == 0) ? q  : (z == 1) ? k  : v;
    const float* B = (z == 0) ? Wq : (z == 1) ? Wk : Wv;
    __nv_bfloat16* Ch = (z == 0) ? Qh : (z == 1) ? Kh : Vh;
    __nv_bfloat16* Cl = (z == 0) ? Ql : (z == 1) ? Kl : Vl;
    float scale = (z == 0) ? 0.125f : 1.0f;
    gemm_core(A, B, nullptr, Ch, Cl, scale, NTOK, DIM, DIM, sm);
}

// Output projection (fp32 out).
__global__ void __launch_bounds__(256, 2)
wo_gemm(const float* __restrict__ A, const float* __restrict__ B,
        float* __restrict__ C)
{
    extern __shared__ float sm[];
    gemm_core(A, B, C, nullptr, nullptr, 1.0f, NTOK, DIM, DIM, sm);
}

// ---------------------------------------------------------------------------
// Flash attention, bf16 tensor cores, 3-term hi/lo split, cp.async
// double-buffered K/V tiles. (unchanged from R4/R5)
// ---------------------------------------------------------------------------
#define RS 72
#define KVSTAGE (4*64*RS)
#define SQH 0
#define SQL (128*RS)
#define SB_TOTAL (2*KVSTAGE)           // 36864 bf16 = 73728 B
#define OKH 0
#define OKL (64*RS)
#define OVH (128*RS)
#define OVL (192*RS)

__global__ void __launch_bounds__(256, 1)
flash_bf16(const __nv_bfloat16* __restrict__ Qh, const __nv_bfloat16* __restrict__ Ql,
           const __nv_bfloat16* __restrict__ Kh, const __nv_bfloat16* __restrict__ Kl,
           const __nv_bfloat16* __restrict__ Vh, const __nv_bfloat16* __restrict__ Vl,
           float* __restrict__ merged, float* __restrict__ attn_out,
           int write_attn, const int* __restrict__ maskedp)
{
    extern __shared__ __nv_bfloat16 sb[];
    const int qt  = gridDim.x - 1 - blockIdx.x;
    const int h   = blockIdx.y;
    const int b   = blockIdx.z;
    const int tid = threadIdx.x;
    const int lane = tid & 31;
    const int w   = tid >> 5;
    const int q0  = qt * 128;
    const int masked = maskedp[0];

    unsigned sbase;
    asm("{ .reg .u64 t; cvta.to.shared.u64 t, %1; cvt.u32.u64 %0, t; }"
        : "=r"(sbase) : "l"(sb));

    const int ktmax = masked ? (2 * qt + 1) : (SEQ / 64 - 1);

    auto stage_off = [](int kt) -> unsigned { return (kt & 1) ? 0u : (unsigned)KVSTAGE; };

    auto prefetch = [&](int t) {
        if (t <= ktmax) {
            unsigned so = stage_off(t);
            int r  = tid >> 3;
            int c8 = (tid & 7) << 3;
            #pragma unroll
            for (int half = 0; half < 2; half++) {
                int rr = r + 32 * half;
                size_t gidx = ((size_t)(b * SEQ + t * 64 + rr) * DIM) + h * HD + c8;
                unsigned sa = sbase + (so + rr * RS + c8) * 2;
                cp_async16(sa + OKH * 2, Kh + gidx);
                cp_async16(sa + OKL * 2, Kl + gidx);
                cp_async16(sa + OVH * 2, Vh + gidx);
                cp_async16(sa + OVL * 2, Vl + gidx);
            }
        }
        cp_commit();
    };

    prefetch(0);
    for (int i = tid; i < 1024; i += 256) {
        int r = i >> 3, c8 = (i & 7) << 3;
        size_t gidx = ((size_t)(b * SEQ + q0 + r) * DIM) + h * HD + c8;
        *(uint4*)(sb + SQH + r * RS + c8) = *(const uint4*)(Qh + gidx);
        *(uint4*)(sb + SQL + r * RS + c8) = *(const uint4*)(Ql + gidx);
    }
    __syncthreads();

    unsigned qf[2][4][4];
    {
        int row  = 16 * w + (lane & 15);
        int coct = (lane >> 4) << 3;
        #pragma unroll
        for (int p = 0; p < 2; p++)
            #pragma unroll
            for (int d = 0; d < 4; d++) {
                unsigned addr = sbase +
                    ((p ? SQL : SQH) + row * RS + d * 16 + coct) * 2;
                ldsm_x4(qf[p][d], addr);
            }
    }
    __syncthreads();
    prefetch(1);

    float o[8][4];
    #pragma unroll
    for (int j = 0; j < 8; j++)
        #pragma unroll
        for (int e = 0; e < 4; e++) o[j][e] = 0.0f;
    float m0 = -1e30f, m1 = -1e30f, l0 = 0.0f, l1 = 0.0f;

    const int r_lo = q0 + 16 * w + (lane >> 2);
    const int r_hi = r_lo + 8;

    for (int kt = 0; kt <= ktmax; kt++) {
        cp_wait<1>();
        __syncthreads();

        const unsigned so = stage_off(kt);
        const int k0 = kt * 64;
        const bool active = !(masked && k0 > q0 + 16 * w + 15);

        if (active) {
            float s[8][4];
            #pragma unroll
            for (int j = 0; j < 8; j++)
                #pragma unroll
                for (int e = 0; e < 4; e++) s[j][e] = 0.0f;

            #pragma unroll
            for (int j = 0; j < 8; j++) {
                unsigned kbh[8], kbl[8];
                int krow = 8 * j + (lane & 7);
                int dct  = (lane >> 3) << 3;
                ldsm_x4(&kbh[0], sbase + (so + OKH + krow * RS + dct) * 2);
                ldsm_x4(&kbh[4], sbase + (so + OKH + krow * RS + 32 + dct) * 2);
                ldsm_x4(&kbl[0], sbase + (so + OKL + krow * RS + dct) * 2);
                ldsm_x4(&kbl[4], sbase + (so + OKL + krow * RS + 32 + dct) * 2);
                #pragma unroll
                for (int d = 0; d < 4; d++) {
                    mma_bf16(s[j], qf[0][d], kbh[2*d], kbh[2*d+1]);
                    mma_bf16(s[j], qf[0][d], kbl[2*d], kbl[2*d+1]);
                    mma_bf16(s[j], qf[1][d], kbh[2*d], kbh[2*d+1]);
                }
            }

            if (masked && k0 + 63 > r_lo) {
                #pragma unroll
                for (int j = 0; j < 8; j++) {
                    int cc = k0 + 8 * j + 2 * (lane & 3);
                    if (cc     > r_lo) s[j][0] = -1e30f;
                    if (cc + 1 > r_lo) s[j][1] = -1e30f;
                    if (cc     > r_hi) s[j][2] = -1e30f;
                    if (cc + 1 > r_hi) s[j][3] = -1e30f;
                }
            }

            float mt0 = -1e30f, mt1 = -1e30f;
            #pragma unroll
            for (int j = 0; j < 8; j++) {
                mt0 = fmaxf(mt0, fmaxf(s[j][0], s[j][1]));
                mt1 = fmaxf(mt1, fmaxf(s[j][2], s[j][3]));
            }
            mt0 = fmaxf(mt0, __shfl_xor_sync(0xffffffffu, mt0, 1));
            mt0 = fmaxf(mt0, __shfl_xor_sync(0xffffffffu, mt0, 2));
            mt1 = fmaxf(mt1, __shfl_xor_sync(0xffffffffu, mt1, 1));
            mt1 = fmaxf(mt1, __shfl_xor_sync(0xffffffffu, mt1, 2));
            float mn0 = fmaxf(m0, mt0), mn1 = fmaxf(m1, mt1);
            float a0 = __expf(m0 - mn0), a1 = __expf(m1 - mn1);
            m0 = mn0; m1 = mn1;

            float rs0 = 0.0f, rs1 = 0.0f;
            unsigned pah[4][4], pal[4][4];
            #pragma unroll
            for (int j = 0; j < 8; j++) {
                float p0 = __expf(s[j][0] - mn0);
                float p1 = __expf(s[j][1] - mn0);
                float p2 = __expf(s[j][2] - mn1);
                float p3 = __expf(s[j][3] - mn1);
                rs0 += p0 + p1; rs1 += p2 + p3;
                unsigned h01 = packbf2(p1, p0);
                unsigned h23 = packbf2(p3, p2);
                float q0f = __uint_as_float(h01 << 16);
                float q1f = __uint_as_float(h01 & 0xffff0000u);
                float q2f = __uint_as_float(h23 << 16);
                float q3f = __uint_as_float(h23 & 0xffff0000u);
                unsigned lo01 = packbf2(p1 - q1f, p0 - q0f);
                unsigned lo23 = packbf2(p3 - q3f, p2 - q2f);
                int t = j >> 1, half = j & 1;
                pah[t][2 * half + 0] = h01;
                pah[t][2 * half + 1] = h23;
                pal[t][2 * half + 0] = lo01;
                pal[t][2 * half + 1] = lo23;
            }
            rs0 += __shfl_xor_sync(0xffffffffu, rs0, 1);
            rs0 += __shfl_xor_sync(0xffffffffu, rs0, 2);
            rs1 += __shfl_xor_sync(0xffffffffu, rs1, 1);
            rs1 += __shfl_xor_sync(0xffffffffu, rs1, 2);
            l0 = l0 * a0 + rs0;
            l1 = l1 * a1 + rs1;
            #pragma unroll
            for (int j = 0; j < 8; j++) {
                o[j][0] *= a0; o[j][1] *= a0;
                o[j][2] *= a1; o[j][3] *= a1;
            }

            #pragma unroll
            for (int jn = 0; jn < 8; jn++) {
                unsigned vbh[8], vbl[8];
                ldsm_x4_t(&vbh[0], sbase + (so + OVH + lane * RS + 8 * jn) * 2);
                ldsm_x4_t(&vbh[4], sbase + (so + OVH + (32 + lane) * RS + 8 * jn) * 2);
                ldsm_x4_t(&vbl[0], sbase + (so + OVL + lane * RS + 8 * jn) * 2);
                ldsm_x4_t(&vbl[4], sbase + (so + OVL + (32 + lane) * RS + 8 * jn) * 2);
                #pragma unroll
                for (int t = 0; t < 4; t++) {
                    mma_bf16(o[jn], pah[t], vbh[2*t], vbh[2*t+1]);
                    mma_bf16(o[jn], pah[t], vbl[2*t], vbl[2*t+1]);
                    mma_bf16(o[jn], pal[t], vbh[2*t], vbh[2*t+1]);
                }
            }
        }

        __syncthreads();
        prefetch(kt + 2);
    }

    float il0 = 1.0f / l0, il1 = 1.0f / l1;
    #pragma unroll
    for (int jn = 0; jn < 8; jn++) {
        int col = 8 * jn + 2 * (lane & 3);
        float f00 = o[jn][0] * il0, f01 = o[jn][1] * il0;
        float f10 = o[jn][2] * il1, f11 = o[jn][3] * il1;
        *(float2*)(merged + ((size_t)(b * SEQ + r_lo) * DIM) + h * HD + col) =
            make_float2(f00, f01);
        *(float2*)(merged + ((size_t)(b * SEQ + r_hi) * DIM) + h * HD + col) =
            make_float2(f10, f11);
        if (write_attn) {
            *(float2*)(attn_out + (((size_t)(b * NH + h) * SEQ + r_lo) * HD) + col) =
                make_float2(f00, f01);
            *(float2*)(attn_out + (((size_t)(b * NH + h) * SEQ + r_hi) * HD) + col) =
                make_float2(f10, f11);
        }
    }
}

// ---------------------------------------------------------------------------
extern "C" void kernel_launch(void* const* d_in, const int* in_sizes, int n_in,
                              void* d_out, int out_size)
{
    const float* q  = (const float*)d_in[0];
    const float* k  = (const float*)d_in[1];
    const float* v  = (const float*)d_in[2];
    const float* Wq = (const float*)d_in[3];
    const float* Wk = (const float*)d_in[4];
    const float* Wv = (const float*)d_in[5];
    const float* Wo = (const float*)d_in[6];
    const int* masked = (const int*)d_in[7];
    float* out = (float*)d_out;

    float* pM;
    __nv_bfloat16 *pQh, *pQl, *pKh, *pKl, *pVh, *pVl;
    cudaGetSymbolAddress((void**)&pM,  g_M);
    cudaGetSymbolAddress((void**)&pQh, g_Qh);
    cudaGetSymbolAddress((void**)&pQl, g_Ql);
    cudaGetSymbolAddress((void**)&pKh, g_Kh);
    cudaGetSymbolAddress((void**)&pKl, g_Kl);
    cudaGetSymbolAddress((void**)&pVh, g_Vh);
    cudaGetSymbolAddress((void**)&pVl, g_Vl);

    cudaFuncSetAttribute(qkv_gemm, cudaFuncAttributeMaxDynamicSharedMemorySize,
                         GEMM_SMEM);
    cudaFuncSetAttribute(wo_gemm, cudaFuncAttributeMaxDynamicSharedMemorySize,
                         GEMM_SMEM);

    // Fused Q/K/V projections (one launch, grid.z = 3)
    dim3 gQKV(DIM / GBN, NTOK / GBM, 3);   // (8, 32, 3) = 768 CTAs
    qkv_gemm<<<gQKV, 256, GEMM_SMEM>>>(q, k, v, Wq, Wk, Wv,
                                       pQh, pQl, pKh, pKl, pVh, pVl);

    // Attention
    int write_attn = (out_size >= (int)(2 * NELEM)) ? 1 : 0;
    float* attn_ptr = out + NELEM;
    size_t fl_smem = (size_t)SB_TOTAL * sizeof(__nv_bfloat16);
    cudaFuncSetAttribute(flash_bf16, cudaFuncAttributeMaxDynamicSharedMemorySize,
                         (int)fl_smem);
    dim3 gAttn(SEQ / 128, NH, BSZ);
    flash_bf16<<<gAttn, 256, fl_smem>>>(pQh, pQl, pKh, pKl, pVh, pVl,
                                        pM, attn_ptr, write_attn, masked);

    // Output projection
    dim3 gWo(DIM / GBN, NTOK / GBM);
    wo_gemm<<<gWo, 256, GEMM_SMEM>>>(pM, Wo, out);
}

// round 7
// speedup vs baseline: 1.1171x; 1.1098x over previous
#include <cuda_runtime.h>
#include <cuda_bf16.h>
#include <math.h>

#define BSZ 2
#define SEQ 2048
#define DIM 1024
#define NH  16
#define HD  64
#define NTOK (BSZ*SEQ)            // 4096
#define NELEM ((size_t)NTOK*DIM)  // 4,194,304

// Scratch (allocation-free rule: __device__ globals)
__device__ float g_M[NELEM];               // merged attention output [B,S,H*HD]
__device__ __nv_bfloat16 g_Qh[NELEM], g_Ql[NELEM];
__device__ __nv_bfloat16 g_Kh[NELEM], g_Kl[NELEM];
__device__ __nv_bfloat16 g_Vh[NELEM], g_Vl[NELEM];

// ---------------------------------------------------------------------------
// small PTX helpers
// ---------------------------------------------------------------------------
__device__ __forceinline__ unsigned f2tf32(float f) {
    unsigned r;
    asm("cvt.rna.tf32.f32 %0, %1;" : "=r"(r) : "f"(f));
    return r;
}
__device__ __forceinline__ unsigned packbf2(float hi, float lo) {
    unsigned d;
    asm("cvt.rn.bf16x2.f32 %0, %1, %2;" : "=r"(d) : "f"(hi), "f"(lo));
    return d;
}
__device__ __forceinline__ void cp_async16(unsigned smem_addr, const void* gptr) {
    asm volatile("cp.async.cg.shared.global [%0], [%1], 16;\n"
                 :: "r"(smem_addr), "l"(gptr));
}
__device__ __forceinline__ void cp_commit() {
    asm volatile("cp.async.commit_group;\n");
}
template <int N>
__device__ __forceinline__ void cp_wait() {
    asm volatile("cp.async.wait_group %0;\n" :: "n"(N));
}
__device__ __forceinline__ void ldsm_x4(unsigned* r, unsigned addr) {
    asm volatile("ldmatrix.sync.aligned.m8n8.x4.shared.b16 {%0,%1,%2,%3}, [%4];"
                 : "=r"(r[0]), "=r"(r[1]), "=r"(r[2]), "=r"(r[3]) : "r"(addr));
}
__device__ __forceinline__ void ldsm_x4_t(unsigned* r, unsigned addr) {
    asm volatile("ldmatrix.sync.aligned.m8n8.x4.trans.shared.b16 {%0,%1,%2,%3}, [%4];"
                 : "=r"(r[0]), "=r"(r[1]), "=r"(r[2]), "=r"(r[3]) : "r"(addr));
}
__device__ __forceinline__ void mma_bf16(float* c, const unsigned* a,
                                         unsigned b0, unsigned b1) {
    asm volatile(
        "mma.sync.aligned.m16n8k16.row.col.f32.bf16.bf16.f32 "
        "{%0,%1,%2,%3},{%4,%5,%6,%7},{%8,%9},{%0,%1,%2,%3};"
        : "+f"(c[0]), "+f"(c[1]), "+f"(c[2]), "+f"(c[3])
        : "r"(a[0]), "r"(a[1]), "r"(a[2]), "r"(a[3]), "r"(b0), "r"(b1));
}

// ---------------------------------------------------------------------------
// TF32 GEMM core (R4-proven config): 128x128 block, GBK=32, 2-stage
// cp.async pipeline, 8 warps, 64x32 warp tile, in-loop tf32 cvt.
// ---------------------------------------------------------------------------
#define GBM 128
#define GBN 128
#define GBK 32
#define ASTRIDE 36
#define BSTRIDE 136
#define STAGE_FLOATS (GBM*ASTRIDE + GBK*BSTRIDE)   // 8960
#define GEMM_SMEM (2*STAGE_FLOATS*4)               // 71680 B

__device__ __forceinline__ void gemm_core(
    const float* __restrict__ A, const float* __restrict__ B,
    float* __restrict__ Cf,
    __nv_bfloat16* __restrict__ Ch, __nv_bfloat16* __restrict__ Cl,
    float scale, int M, int N, int K, float* sm)
{
    const int tid  = threadIdx.x;
    const int lane = tid & 31;
    const int warp = tid >> 5;
    const int wm   = warp >> 2;
    const int wn   = warp & 3;

    const int bRow = blockIdx.y;
    const int bCol = blockIdx.x;

    const float* Ab = A + (size_t)bRow * GBM * K;
    const float* Bb = B + (size_t)bCol * GBN;

    unsigned smem_base;
    asm("{ .reg .u64 t; cvta.to.shared.u64 t, %1; cvt.u32.u64 %0, t; }"
        : "=r"(smem_base) : "l"(sm));

    const int aRowL = tid >> 3;
    const int aColL = (tid & 7) * 4;
    const int bRowL = tid >> 5;
    const int bColL = (tid & 31) * 4;

    float c[4][4][4];
    #pragma unroll
    for (int mt = 0; mt < 4; mt++)
        #pragma unroll
        for (int nt = 0; nt < 4; nt++)
            #pragma unroll
            for (int e = 0; e < 4; e++) c[mt][nt][e] = 0.0f;

    const int niter = K / GBK;

    auto load_stage = [&](int iter, int buf) {
        const int k0 = iter * GBK;
        unsigned aBase = smem_base + (unsigned)(buf * STAGE_FLOATS) * 4u;
        unsigned bBase = aBase + GBM * ASTRIDE * 4u;
        #pragma unroll
        for (int it = 0; it < 4; it++) {
            int r = aRowL + it * 32;
            cp_async16(aBase + (r * ASTRIDE + aColL) * 4u,
                       Ab + (size_t)r * K + k0 + aColL);
        }
        #pragma unroll
        for (int it = 0; it < 4; it++) {
            int r = bRowL + it * 8;
            cp_async16(bBase + (r * BSTRIDE + bColL) * 4u,
                       Bb + (size_t)(k0 + r) * N + bColL);
        }
    };

    load_stage(0, 0); cp_commit();
    load_stage(1, 1); cp_commit();

    const int g  = lane >> 2;
    const int tg = lane & 3;

    for (int i = 0; i < niter; i++) {
        cp_wait<1>();
        __syncthreads();

        const int buf = i & 1;
        const float* As = sm + buf * STAGE_FLOATS;
        const float* Bs = As + GBM * ASTRIDE;

        #pragma unroll
        for (int kk = 0; kk < GBK / 8; kk++) {
            unsigned af[4][4], bf[4][2];
            const int c0 = kk * 8 + tg;
            #pragma unroll
            for (int mt = 0; mt < 4; mt++) {
                int r0 = wm * 64 + mt * 16 + g;
                af[mt][0] = f2tf32(As[r0       * ASTRIDE + c0]);
                af[mt][1] = f2tf32(As[(r0 + 8) * ASTRIDE + c0]);
                af[mt][2] = f2tf32(As[r0       * ASTRIDE + c0 + 4]);
                af[mt][3] = f2tf32(As[(r0 + 8) * ASTRIDE + c0 + 4]);
            }
            #pragma unroll
            for (int nt = 0; nt < 4; nt++) {
                int col = wn * 32 + nt * 8 + g;
                bf[nt][0] = f2tf32(Bs[c0       * BSTRIDE + col]);
                bf[nt][1] = f2tf32(Bs[(c0 + 4) * BSTRIDE + col]);
            }
            #pragma unroll
            for (int mt = 0; mt < 4; mt++)
                #pragma unroll
                for (int nt = 0; nt < 4; nt++) {
                    asm volatile(
                        "mma.sync.aligned.m16n8k8.row.col.f32.tf32.tf32.f32 "
                        "{%0,%1,%2,%3},{%4,%5,%6,%7},{%8,%9},{%0,%1,%2,%3};\n"
                        : "+f"(c[mt][nt][0]), "+f"(c[mt][nt][1]),
                          "+f"(c[mt][nt][2]), "+f"(c[mt][nt][3])
                        : "r"(af[mt][0]), "r"(af[mt][1]),
                          "r"(af[mt][2]), "r"(af[mt][3]),
                          "r"(bf[nt][0]), "r"(bf[nt][1]));
                }
        }
        __syncthreads();
        if (i + 2 < niter) load_stage(i + 2, buf);
        cp_commit();
    }

    // Epilogue
    if (Ch) {
        #pragma unroll
        for (int mt = 0; mt < 4; mt++) {
            int r0 = bRow * GBM + wm * 64 + mt * 16 + g;
            #pragma unroll
            for (int nt = 0; nt < 4; nt++) {
                int col = bCol * GBN + wn * 32 + nt * 8 + 2 * tg;
                #pragma unroll
                for (int half = 0; half < 2; half++) {
                    size_t off = (size_t)(r0 + 8 * half) * N + col;
                    float y0 = c[mt][nt][2 * half + 0] * scale;
                    float y1 = c[mt][nt][2 * half + 1] * scale;
                    unsigned hi = packbf2(y1, y0);
                    float h0 = __uint_as_float(hi << 16);
                    float h1 = __uint_as_float(hi & 0xffff0000u);
                    unsigned lo = packbf2(y1 - h1, y0 - h0);
                    *(unsigned*)(Ch + off) = hi;
                    *(unsigned*)(Cl + off) = lo;
                }
            }
        }
    } else {
        float* Cb = Cf + (size_t)bRow * GBM * N + bCol * GBN;
        #pragma unroll
        for (int mt = 0; mt < 4; mt++) {
            int r0 = wm * 64 + mt * 16 + g;
            #pragma unroll
            for (int nt = 0; nt < 4; nt++) {
                int col = wn * 32 + nt * 8 + 2 * tg;
                *(float2*)(Cb + (size_t)r0 * N + col) =
                    make_float2(c[mt][nt][0], c[mt][nt][1]);
                *(float2*)(Cb + (size_t)(r0 + 8) * N + col) =
                    make_float2(c[mt][nt][2], c[mt][nt][3]);
            }
        }
    }
}

// Fused Q/K/V projections: grid.z selects the GEMM.
__global__ void __launch_bounds__(256, 2)
qkv_gemm(const float* __restrict__ q, const float* __restrict__ k,
         const float* __restrict__ v,
         const float* __restrict__ Wq, const float* __restrict__ Wk,
         const float* __restrict__ Wv,
         __nv_bfloat16* Qh, __nv_bfloat16* Ql,
         __nv_bfloat16* Kh, __nv_bfloat16* Kl,
         __nv_bfloat16* Vh, __nv_bfloat16* Vl)
{
    extern __shared__ float sm[];
    const int z = blockIdx.z;
    const float* A = (z == 0) ? q  : (z == 1) ? k  : v;
    const float* B = (z == 0) ? Wq : (z == 1) ? Wk : Wv;
    __nv_bfloat16* Ch = (z == 0) ? Qh : (z == 1) ? Kh : Vh;
    __nv_bfloat16* Cl = (z == 0) ? Ql : (z == 1) ? Kl : Vl;
    float scale = (z == 0) ? 0.125f : 1.0f;
    gemm_core(A, B, nullptr, Ch, Cl, scale, NTOK, DIM, DIM, sm);
}

__global__ void __launch_bounds__(256, 2)
wo_gemm(const float* __restrict__ A, const float* __restrict__ B,
        float* __restrict__ C)
{
    extern __shared__ float sm[];
    gemm_core(A, B, C, nullptr, nullptr, 1.0f, NTOK, DIM, DIM, sm);
}

// ---------------------------------------------------------------------------
// Flash attention, bf16 tensor cores, 3-term hi/lo split.
// 128-thread CTAs (4 warps) over 64 q-rows -> 2 CTAs/SM co-residency.
// Q fragments loaded directly from gmem (no Q smem). 2-stage cp.async KV.
// ---------------------------------------------------------------------------
#define RS 72
#define KVSTAGE (4*64*RS)              // 18432 bf16 per stage
#define SB_TOTAL (2*KVSTAGE)           // 36864 bf16 = 73728 B
#define OKH 0
#define OKL (64*RS)
#define OVH (128*RS)
#define OVL (192*RS)

__global__ void __launch_bounds__(128, 2)
flash_bf16(const __nv_bfloat16* __restrict__ Qh, const __nv_bfloat16* __restrict__ Ql,
           const __nv_bfloat16* __restrict__ Kh, const __nv_bfloat16* __restrict__ Kl,
           const __nv_bfloat16* __restrict__ Vh, const __nv_bfloat16* __restrict__ Vl,
           float* __restrict__ merged, float* __restrict__ attn_out,
           int write_attn, const int* __restrict__ maskedp)
{
    extern __shared__ __nv_bfloat16 sb[];
    const int qt  = gridDim.x - 1 - blockIdx.x;   // heavy blocks first
    const int h   = blockIdx.y;
    const int b   = blockIdx.z;
    const int tid = threadIdx.x;
    const int lane = tid & 31;
    const int w   = tid >> 5;                     // 0..3
    const int q0  = qt * 64;
    const int masked = maskedp[0];

    unsigned sbase;
    asm("{ .reg .u64 t; cvta.to.shared.u64 t, %1; cvt.u32.u64 %0, t; }"
        : "=r"(sbase) : "l"(sb));

    const int ktmax = masked ? qt : (SEQ / 64 - 1);

    auto stage_off = [](int kt) -> unsigned { return (kt & 1) ? (unsigned)KVSTAGE : 0u; };

    // cooperative cp.async prefetch of K/V tile t (16 x 16B per thread)
    auto prefetch = [&](int t) {
        if (t <= ktmax) {
            unsigned so = stage_off(t);
            int r  = tid >> 3;               // 0..15 (+16,+32,+48)
            int c8 = (tid & 7) << 3;
            #pragma unroll
            for (int quarter = 0; quarter < 4; quarter++) {
                int rr = r + 16 * quarter;
                size_t gidx = ((size_t)(b * SEQ + t * 64 + rr) * DIM) + h * HD + c8;
                unsigned sa = sbase + (so + rr * RS + c8) * 2;
                cp_async16(sa + OKH * 2, Kh + gidx);
                cp_async16(sa + OKL * 2, Kl + gidx);
                cp_async16(sa + OVH * 2, Vh + gidx);
                cp_async16(sa + OVL * 2, Vl + gidx);
            }
        }
        cp_commit();
    };

    prefetch(0);
    prefetch(1);

    // ---- Q A-frags directly from gmem: [plane][dstep][4regs] ----
    // m16n8k16 A-frag: a0=(g, 2tg:2tg+1), a1=(g+8, ..), a2=(g, 2tg+8:+9), a3=(g+8, ..)
    unsigned qf[2][4][4];
    {
        const int g  = lane >> 2;
        const int tg = lane & 3;
        const int row0 = q0 + 16 * w + g;
        size_t base0 = ((size_t)(b * SEQ + row0)     * DIM) + h * HD;
        size_t base1 = ((size_t)(b * SEQ + row0 + 8) * DIM) + h * HD;
        #pragma unroll
        for (int d = 0; d < 4; d++) {
            int c0 = 16 * d + 2 * tg;
            qf[0][d][0] = *(const unsigned*)(Qh + base0 + c0);
            qf[0][d][1] = *(const unsigned*)(Qh + base1 + c0);
            qf[0][d][2] = *(const unsigned*)(Qh + base0 + c0 + 8);
            qf[0][d][3] = *(const unsigned*)(Qh + base1 + c0 + 8);
            qf[1][d][0] = *(const unsigned*)(Ql + base0 + c0);
            qf[1][d][1] = *(const unsigned*)(Ql + base1 + c0);
            qf[1][d][2] = *(const unsigned*)(Ql + base0 + c0 + 8);
            qf[1][d][3] = *(const unsigned*)(Ql + base1 + c0 + 8);
        }
    }

    float o[8][4];
    #pragma unroll
    for (int j = 0; j < 8; j++)
        #pragma unroll
        for (int e = 0; e < 4; e++) o[j][e] = 0.0f;
    float m0 = -1e30f, m1 = -1e30f, l0 = 0.0f, l1 = 0.0f;

    const int r_lo = q0 + 16 * w + (lane >> 2);
    const int r_hi = r_lo + 8;

    for (int kt = 0; kt <= ktmax; kt++) {
        cp_wait<1>();
        __syncthreads();

        const unsigned so = stage_off(kt);
        const int k0 = kt * 64;

        // ---- QK^T ----
        float s[8][4];
        #pragma unroll
        for (int j = 0; j < 8; j++)
            #pragma unroll
            for (int e = 0; e < 4; e++) s[j][e] = 0.0f;

        #pragma unroll
        for (int j = 0; j < 8; j++) {
            unsigned kbh[8], kbl[8];
            int krow = 8 * j + (lane & 7);
            int dct  = (lane >> 3) << 3;
            ldsm_x4(&kbh[0], sbase + (so + OKH + krow * RS + dct) * 2);
            ldsm_x4(&kbh[4], sbase + (so + OKH + krow * RS + 32 + dct) * 2);
            ldsm_x4(&kbl[0], sbase + (so + OKL + krow * RS + dct) * 2);
            ldsm_x4(&kbl[4], sbase + (so + OKL + krow * RS + 32 + dct) * 2);
            #pragma unroll
            for (int d = 0; d < 4; d++) {
                mma_bf16(s[j], qf[0][d], kbh[2*d], kbh[2*d+1]);
                mma_bf16(s[j], qf[0][d], kbl[2*d], kbl[2*d+1]);
                mma_bf16(s[j], qf[1][d], kbh[2*d], kbh[2*d+1]);
            }
        }

        // ---- causal mask (diagonal tile only) ----
        if (masked && kt == qt) {
            #pragma unroll
            for (int j = 0; j < 8; j++) {
                int cc = k0 + 8 * j + 2 * (lane & 3);
                if (cc     > r_lo) s[j][0] = -1e30f;
                if (cc + 1 > r_lo) s[j][1] = -1e30f;
                if (cc     > r_hi) s[j][2] = -1e30f;
                if (cc + 1 > r_hi) s[j][3] = -1e30f;
            }
        }

        // ---- online softmax ----
        float mt0 = -1e30f, mt1 = -1e30f;
        #pragma unroll
        for (int j = 0; j < 8; j++) {
            mt0 = fmaxf(mt0, fmaxf(s[j][0], s[j][1]));
            mt1 = fmaxf(mt1, fmaxf(s[j][2], s[j][3]));
        }
        mt0 = fmaxf(mt0, __shfl_xor_sync(0xffffffffu, mt0, 1));
        mt0 = fmaxf(mt0, __shfl_xor_sync(0xffffffffu, mt0, 2));
        mt1 = fmaxf(mt1, __shfl_xor_sync(0xffffffffu, mt1, 1));
        mt1 = fmaxf(mt1, __shfl_xor_sync(0xffffffffu, mt1, 2));
        float mn0 = fmaxf(m0, mt0), mn1 = fmaxf(m1, mt1);
        float a0 = __expf(m0 - mn0), a1 = __expf(m1 - mn1);
        m0 = mn0; m1 = mn1;

        float rs0 = 0.0f, rs1 = 0.0f;
        unsigned pah[4][4], pal[4][4];
        #pragma unroll
        for (int j = 0; j < 8; j++) {
            float p0 = __expf(s[j][0] - mn0);
            float p1 = __expf(s[j][1] - mn0);
            float p2 = __expf(s[j][2] - mn1);
            float p3 = __expf(s[j][3] - mn1);
            rs0 += p0 + p1; rs1 += p2 + p3;
            unsigned h01 = packbf2(p1, p0);
            unsigned h23 = packbf2(p3, p2);
            float q0f = __uint_as_float(h01 << 16);
            float q1f = __uint_as_float(h01 & 0xffff0000u);
            float q2f = __uint_as_float(h23 << 16);
            float q3f = __uint_as_float(h23 & 0xffff0000u);
            unsigned lo01 = packbf2(p1 - q1f, p0 - q0f);
            unsigned lo23 = packbf2(p3 - q3f, p2 - q2f);
            int t = j >> 1, half = j & 1;
            pah[t][2 * half + 0] = h01;
            pah[t][2 * half + 1] = h23;
            pal[t][2 * half + 0] = lo01;
            pal[t][2 * half + 1] = lo23;
        }
        rs0 += __shfl_xor_sync(0xffffffffu, rs0, 1);
        rs0 += __shfl_xor_sync(0xffffffffu, rs0, 2);
        rs1 += __shfl_xor_sync(0xffffffffu, rs1, 1);
        rs1 += __shfl_xor_sync(0xffffffffu, rs1, 2);
        l0 = l0 * a0 + rs0;
        l1 = l1 * a1 + rs1;
        #pragma unroll
        for (int j = 0; j < 8; j++) {
            o[j][0] *= a0; o[j][1] *= a0;
            o[j][2] *= a1; o[j][3] *= a1;
        }

        // ---- PV ----
        #pragma unroll
        for (int jn = 0; jn < 8; jn++) {
            unsigned vbh[8], vbl[8];
            ldsm_x4_t(&vbh[0], sbase + (so + OVH + lane * RS + 8 * jn) * 2);
            ldsm_x4_t(&vbh[4], sbase + (so + OVH + (32 + lane) * RS + 8 * jn) * 2);
            ldsm_x4_t(&vbl[0], sbase + (so + OVL + lane * RS + 8 * jn) * 2);
            ldsm_x4_t(&vbl[4], sbase + (so + OVL + (32 + lane) * RS + 8 * jn) * 2);
            #pragma unroll
            for (int t = 0; t < 4; t++) {
                mma_bf16(o[jn], pah[t], vbh[2*t], vbh[2*t+1]);
                mma_bf16(o[jn], pah[t], vbl[2*t], vbl[2*t+1]);
                mma_bf16(o[jn], pal[t], vbh[2*t], vbh[2*t+1]);
            }
        }

        __syncthreads();      // all warps done reading stage(kt)
        prefetch(kt + 2);     // refill the stage we just consumed
    }

    // ---- finalize + write ----
    float il0 = 1.0f / l0, il1 = 1.0f / l1;
    #pragma unroll
    for (int jn = 0; jn < 8; jn++) {
        int col = 8 * jn + 2 * (lane & 3);
        float f00 = o[jn][0] * il0, f01 = o[jn][1] * il0;
        float f10 = o[jn][2] * il1, f11 = o[jn][3] * il1;
        *(float2*)(merged + ((size_t)(b * SEQ + r_lo) * DIM) + h * HD + col) =
            make_float2(f00, f01);
        *(float2*)(merged + ((size_t)(b * SEQ + r_hi) * DIM) + h * HD + col) =
            make_float2(f10, f11);
        if (write_attn) {
            *(float2*)(attn_out + (((size_t)(b * NH + h) * SEQ + r_lo) * HD) + col) =
                make_float2(f00, f01);
            *(float2*)(attn_out + (((size_t)(b * NH + h) * SEQ + r_hi) * HD) + col) =
                make_float2(f10, f11);
        }
    }
}

// ---------------------------------------------------------------------------
extern "C" void kernel_launch(void* const* d_in, const int* in_sizes, int n_in,
                              void* d_out, int out_size)
{
    const float* q  = (const float*)d_in[0];
    const float* k  = (const float*)d_in[1];
    const float* v  = (const float*)d_in[2];
    const float* Wq = (const float*)d_in[3];
    const float* Wk = (const float*)d_in[4];
    const float* Wv = (const float*)d_in[5];
    const float* Wo = (const float*)d_in[6];
    const int* masked = (const int*)d_in[7];
    float* out = (float*)d_out;

    float* pM;
    __nv_bfloat16 *pQh, *pQl, *pKh, *pKl, *pVh, *pVl;
    cudaGetSymbolAddress((void**)&pM,  g_M);
    cudaGetSymbolAddress((void**)&pQh, g_Qh);
    cudaGetSymbolAddress((void**)&pQl, g_Ql);
    cudaGetSymbolAddress((void**)&pKh, g_Kh);
    cudaGetSymbolAddress((void**)&pKl, g_Kl);
    cudaGetSymbolAddress((void**)&pVh, g_Vh);
    cudaGetSymbolAddress((void**)&pVl, g_Vl);

    cudaFuncSetAttribute(qkv_gemm, cudaFuncAttributeMaxDynamicSharedMemorySize,
                         GEMM_SMEM);
    cudaFuncSetAttribute(wo_gemm, cudaFuncAttributeMaxDynamicSharedMemorySize,
                         GEMM_SMEM);

    // Fused Q/K/V projections (R4-proven GEMM core)
    dim3 gQKV(DIM / GBN, NTOK / GBM, 3);   // (8, 32, 3)
    qkv_gemm<<<gQKV, 256, GEMM_SMEM>>>(q, k, v, Wq, Wk, Wv,
                                       pQh, pQl, pKh, pKl, pVh, pVl);

    // Attention: 128-thread CTAs, 64 q-rows each, 2 CTAs/SM
    int write_attn = (out_size >= (int)(2 * NELEM)) ? 1 : 0;
    float* attn_ptr = out + NELEM;
    size_t fl_smem = (size_t)SB_TOTAL * sizeof(__nv_bfloat16);
    cudaFuncSetAttribute(flash_bf16, cudaFuncAttributeMaxDynamicSharedMemorySize,
                         (int)fl_smem);
    dim3 gAttn(SEQ / 64, NH, BSZ);         // (32, 16, 2) = 1024 CTAs
    flash_bf16<<<gAttn, 128, fl_smem>>>(pQh, pQl, pKh, pKl, pVh, pVl,
                                        pM, attn_ptr, write_attn, masked);

    // Output projection
    dim3 gWo(DIM / GBN, NTOK / GBM);
    wo_gemm<<<gWo, 256, GEMM_SMEM>>>(pM, Wo, out);
}

// round 8
// speedup vs baseline: 1.1406x; 1.0210x over previous
#include <cuda_runtime.h>
#include <cuda_bf16.h>
#include <math.h>

#define BSZ 2
#define SEQ 2048
#define DIM 1024
#define NH  16
#define HD  64
#define NTOK (BSZ*SEQ)            // 4096
#define NELEM ((size_t)NTOK*DIM)  // 4,194,304

// Scratch (allocation-free rule: __device__ globals)
__device__ float g_M[NELEM];               // merged attention output [B,S,H*HD]
__device__ __nv_bfloat16 g_Qh[NELEM], g_Ql[NELEM];
__device__ __nv_bfloat16 g_Kh[NELEM], g_Kl[NELEM];
__device__ __nv_bfloat16 g_Vh[NELEM], g_Vl[NELEM];

// ---------------------------------------------------------------------------
// small PTX helpers
// ---------------------------------------------------------------------------
__device__ __forceinline__ unsigned f2tf32(float f) {
    unsigned r;
    asm("cvt.rna.tf32.f32 %0, %1;" : "=r"(r) : "f"(f));
    return r;
}
__device__ __forceinline__ unsigned packbf2(float hi, float lo) {
    unsigned d;
    asm("cvt.rn.bf16x2.f32 %0, %1, %2;" : "=r"(d) : "f"(hi), "f"(lo));
    return d;
}
__device__ __forceinline__ void cp_async16(unsigned smem_addr, const void* gptr) {
    asm volatile("cp.async.cg.shared.global [%0], [%1], 16;\n"
                 :: "r"(smem_addr), "l"(gptr));
}
__device__ __forceinline__ void cp_commit() {
    asm volatile("cp.async.commit_group;\n");
}
template <int N>
__device__ __forceinline__ void cp_wait() {
    asm volatile("cp.async.wait_group %0;\n" :: "n"(N));
}
__device__ __forceinline__ void ldsm_x4(unsigned* r, unsigned addr) {
    asm volatile("ldmatrix.sync.aligned.m8n8.x4.shared.b16 {%0,%1,%2,%3}, [%4];"
                 : "=r"(r[0]), "=r"(r[1]), "=r"(r[2]), "=r"(r[3]) : "r"(addr));
}
__device__ __forceinline__ void ldsm_x4_t(unsigned* r, unsigned addr) {
    asm volatile("ldmatrix.sync.aligned.m8n8.x4.trans.shared.b16 {%0,%1,%2,%3}, [%4];"
                 : "=r"(r[0]), "=r"(r[1]), "=r"(r[2]), "=r"(r[3]) : "r"(addr));
}
__device__ __forceinline__ void mma_bf16(float* c, const unsigned* a,
                                         unsigned b0, unsigned b1) {
    asm volatile(
        "mma.sync.aligned.m16n8k16.row.col.f32.bf16.bf16.f32 "
        "{%0,%1,%2,%3},{%4,%5,%6,%7},{%8,%9},{%0,%1,%2,%3};"
        : "+f"(c[0]), "+f"(c[1]), "+f"(c[2]), "+f"(c[3])
        : "r"(a[0]), "r"(a[1]), "r"(a[2]), "r"(a[3]), "r"(b0), "r"(b1));
}

// ---------------------------------------------------------------------------
// TF32 GEMM core, retiled for co-residency: 64x128 CTA tile, 128 threads
// (4 warps, 32x64 warp tile), GBK=32, 2-stage cp.async pipeline.
// 4 CTAs/SM -> 4 independent barrier domains.
// ---------------------------------------------------------------------------
#define GBM 64
#define GBN 128
#define GBK 32
#define ASTRIDE 36
#define BSTRIDE 136
#define STAGE_FLOATS (GBM*ASTRIDE + GBK*BSTRIDE)   // 2304+4352 = 6656
#define GEMM_SMEM (2*STAGE_FLOATS*4)               // 53248 B

__device__ __forceinline__ void gemm_core(
    const float* __restrict__ A, const float* __restrict__ B,
    float* __restrict__ Cf,
    __nv_bfloat16* __restrict__ Ch, __nv_bfloat16* __restrict__ Cl,
    float scale, int M, int N, int K, float* sm)
{
    const int tid  = threadIdx.x;
    const int lane = tid & 31;
    const int warp = tid >> 5;           // 0..3
    const int wm   = warp >> 1;          // 0..1  (32 rows)
    const int wn   = warp & 1;           // 0..1  (64 cols)

    const int bRow = blockIdx.y;
    const int bCol = blockIdx.x;

    const float* Ab = A + (size_t)bRow * GBM * K;
    const float* Bb = B + (size_t)bCol * GBN;

    unsigned smem_base;
    asm("{ .reg .u64 t; cvta.to.shared.u64 t, %1; cvt.u32.u64 %0, t; }"
        : "=r"(smem_base) : "l"(sm));

    float c[2][8][4];
    #pragma unroll
    for (int mt = 0; mt < 2; mt++)
        #pragma unroll
        for (int nt = 0; nt < 8; nt++)
            #pragma unroll
            for (int e = 0; e < 4; e++) c[mt][nt][e] = 0.0f;

    const int niter = K / GBK;           // 32

    auto load_stage = [&](int iter, int buf) {
        const int k0 = iter * GBK;
        unsigned aBase = smem_base + (unsigned)(buf * STAGE_FLOATS) * 4u;
        unsigned bBase = aBase + GBM * ASTRIDE * 4u;
        // A: 64 rows x 32 k = 512 float4, 4 per thread
        #pragma unroll
        for (int it = 0; it < 4; it++) {
            int r  = (tid >> 3) + 16 * it;
            int c4 = (tid & 7) * 4;
            cp_async16(aBase + (r * ASTRIDE + c4) * 4u,
                       Ab + (size_t)r * K + k0 + c4);
        }
        // B: 32 rows x 128 n = 1024 float4, 8 per thread
        #pragma unroll
        for (int it = 0; it < 8; it++) {
            int idx = tid + 128 * it;
            int r   = idx >> 5;
            int c4  = (idx & 31) * 4;
            cp_async16(bBase + (r * BSTRIDE + c4) * 4u,
                       Bb + (size_t)(k0 + r) * N + c4);
        }
    };

    load_stage(0, 0); cp_commit();
    load_stage(1, 1); cp_commit();

    const int g  = lane >> 2;
    const int tg = lane & 3;

    for (int i = 0; i < niter; i++) {
        cp_wait<1>();
        __syncthreads();

        const int buf = i & 1;
        const float* As = sm + buf * STAGE_FLOATS;
        const float* Bs = As + GBM * ASTRIDE;

        #pragma unroll
        for (int kk = 0; kk < GBK / 8; kk++) {
            unsigned af[2][4], bf[8][2];
            const int c0 = kk * 8 + tg;
            #pragma unroll
            for (int mt = 0; mt < 2; mt++) {
                int r0 = wm * 32 + mt * 16 + g;
                af[mt][0] = f2tf32(As[r0       * ASTRIDE + c0]);
                af[mt][1] = f2tf32(As[(r0 + 8) * ASTRIDE + c0]);
                af[mt][2] = f2tf32(As[r0       * ASTRIDE + c0 + 4]);
                af[mt][3] = f2tf32(As[(r0 + 8) * ASTRIDE + c0 + 4]);
            }
            #pragma unroll
            for (int nt = 0; nt < 8; nt++) {
                int col = wn * 64 + nt * 8 + g;
                bf[nt][0] = f2tf32(Bs[c0       * BSTRIDE + col]);
                bf[nt][1] = f2tf32(Bs[(c0 + 4) * BSTRIDE + col]);
            }
            #pragma unroll
            for (int mt = 0; mt < 2; mt++)
                #pragma unroll
                for (int nt = 0; nt < 8; nt++) {
                    asm volatile(
                        "mma.sync.aligned.m16n8k8.row.col.f32.tf32.tf32.f32 "
                        "{%0,%1,%2,%3},{%4,%5,%6,%7},{%8,%9},{%0,%1,%2,%3};\n"
                        : "+f"(c[mt][nt][0]), "+f"(c[mt][nt][1]),
                          "+f"(c[mt][nt][2]), "+f"(c[mt][nt][3])
                        : "r"(af[mt][0]), "r"(af[mt][1]),
                          "r"(af[mt][2]), "r"(af[mt][3]),
                          "r"(bf[nt][0]), "r"(bf[nt][1]));
                }
        }
        __syncthreads();
        if (i + 2 < niter) load_stage(i + 2, buf);
        cp_commit();
    }

    // Epilogue
    if (Ch) {
        #pragma unroll
        for (int mt = 0; mt < 2; mt++) {
            int r0 = bRow * GBM + wm * 32 + mt * 16 + g;
            #pragma unroll
            for (int nt = 0; nt < 8; nt++) {
                int col = bCol * GBN + wn * 64 + nt * 8 + 2 * tg;
                #pragma unroll
                for (int half = 0; half < 2; half++) {
                    size_t off = (size_t)(r0 + 8 * half) * N + col;
                    float y0 = c[mt][nt][2 * half + 0] * scale;
                    float y1 = c[mt][nt][2 * half + 1] * scale;
                    unsigned hi = packbf2(y1, y0);
                    float h0 = __uint_as_float(hi << 16);
                    float h1 = __uint_as_float(hi & 0xffff0000u);
                    unsigned lo = packbf2(y1 - h1, y0 - h0);
                    *(unsigned*)(Ch + off) = hi;
                    *(unsigned*)(Cl + off) = lo;
                }
            }
        }
    } else {
        float* Cb = Cf + (size_t)bRow * GBM * N + bCol * GBN;
        #pragma unroll
        for (int mt = 0; mt < 2; mt++) {
            int r0 = wm * 32 + mt * 16 + g;
            #pragma unroll
            for (int nt = 0; nt < 8; nt++) {
                int col = wn * 64 + nt * 8 + 2 * tg;
                *(float2*)(Cb + (size_t)r0 * N + col) =
                    make_float2(c[mt][nt][0], c[mt][nt][1]);
                *(float2*)(Cb + (size_t)(r0 + 8) * N + col) =
                    make_float2(c[mt][nt][2], c[mt][nt][3]);
            }
        }
    }
}

// Fused Q/K/V projections: grid.z selects the GEMM.
__global__ void __launch_bounds__(128, 4)
qkv_gemm(const float* __restrict__ q, const float* __restrict__ k,
         const float* __restrict__ v,
         const float* __restrict__ Wq, const float* __restrict__ Wk,
         const float* __restrict__ Wv,
         __nv_bfloat16* Qh, __nv_bfloat16* Ql,
         __nv_bfloat16* Kh, __nv_bfloat16* Kl,
         __nv_bfloat16* Vh, __nv_bfloat16* Vl)
{
    extern __shared__ float sm[];
    const int z = blockIdx.z;
    const float* A = (z == 0) ? q  : (z == 1) ? k  : v;
    const float* B = (z == 0) ? Wq : (z == 1) ? Wk : Wv;
    __nv_bfloat16* Ch = (z == 0) ? Qh : (z == 1) ? Kh : Vh;
    __nv_bfloat16* Cl = (z == 0) ? Ql : (z == 1) ? Kl : Vl;
    float scale = (z == 0) ? 0.125f : 1.0f;
    gemm_core(A, B, nullptr, Ch, Cl, scale, NTOK, DIM, DIM, sm);
}

__global__ void __launch_bounds__(128, 4)
wo_gemm(const float* __restrict__ A, const float* __restrict__ B,
        float* __restrict__ C)
{
    extern __shared__ float sm[];
    gemm_core(A, B, C, nullptr, nullptr, 1.0f, NTOK, DIM, DIM, sm);
}

// ---------------------------------------------------------------------------
// Flash attention (frozen from R7): bf16 tensor cores, 3-term hi/lo split,
// 128-thread CTAs over 64 q-rows, 2 CTAs/SM, gmem-direct Q frags,
// 2-stage cp.async KV double-buffer.
// ---------------------------------------------------------------------------
#define RS 72
#define KVSTAGE (4*64*RS)              // 18432 bf16 per stage
#define SB_TOTAL (2*KVSTAGE)           // 36864 bf16 = 73728 B
#define OKH 0
#define OKL (64*RS)
#define OVH (128*RS)
#define OVL (192*RS)

__global__ void __launch_bounds__(128, 2)
flash_bf16(const __nv_bfloat16* __restrict__ Qh, const __nv_bfloat16* __restrict__ Ql,
           const __nv_bfloat16* __restrict__ Kh, const __nv_bfloat16* __restrict__ Kl,
           const __nv_bfloat16* __restrict__ Vh, const __nv_bfloat16* __restrict__ Vl,
           float* __restrict__ merged, float* __restrict__ attn_out,
           int write_attn, const int* __restrict__ maskedp)
{
    extern __shared__ __nv_bfloat16 sb[];
    const int qt  = gridDim.x - 1 - blockIdx.x;
    const int h   = blockIdx.y;
    const int b   = blockIdx.z;
    const int tid = threadIdx.x;
    const int lane = tid & 31;
    const int w   = tid >> 5;
    const int q0  = qt * 64;
    const int masked = maskedp[0];

    unsigned sbase;
    asm("{ .reg .u64 t; cvta.to.shared.u64 t, %1; cvt.u32.u64 %0, t; }"
        : "=r"(sbase) : "l"(sb));

    const int ktmax = masked ? qt : (SEQ / 64 - 1);

    auto stage_off = [](int kt) -> unsigned { return (kt & 1) ? (unsigned)KVSTAGE : 0u; };

    auto prefetch = [&](int t) {
        if (t <= ktmax) {
            unsigned so = stage_off(t);
            int r  = tid >> 3;
            int c8 = (tid & 7) << 3;
            #pragma unroll
            for (int quarter = 0; quarter < 4; quarter++) {
                int rr = r + 16 * quarter;
                size_t gidx = ((size_t)(b * SEQ + t * 64 + rr) * DIM) + h * HD + c8;
                unsigned sa = sbase + (so + rr * RS + c8) * 2;
                cp_async16(sa + OKH * 2, Kh + gidx);
                cp_async16(sa + OKL * 2, Kl + gidx);
                cp_async16(sa + OVH * 2, Vh + gidx);
                cp_async16(sa + OVL * 2, Vl + gidx);
            }
        }
        cp_commit();
    };

    prefetch(0);
    prefetch(1);

    unsigned qf[2][4][4];
    {
        const int g  = lane >> 2;
        const int tg = lane & 3;
        const int row0 = q0 + 16 * w + g;
        size_t base0 = ((size_t)(b * SEQ + row0)     * DIM) + h * HD;
        size_t base1 = ((size_t)(b * SEQ + row0 + 8) * DIM) + h * HD;
        #pragma unroll
        for (int d = 0; d < 4; d++) {
            int c0 = 16 * d + 2 * tg;
            qf[0][d][0] = *(const unsigned*)(Qh + base0 + c0);
            qf[0][d][1] = *(const unsigned*)(Qh + base1 + c0);
            qf[0][d][2] = *(const unsigned*)(Qh + base0 + c0 + 8);
            qf[0][d][3] = *(const unsigned*)(Qh + base1 + c0 + 8);
            qf[1][d][0] = *(const unsigned*)(Ql + base0 + c0);
            qf[1][d][1] = *(const unsigned*)(Ql + base1 + c0);
            qf[1][d][2] = *(const unsigned*)(Ql + base0 + c0 + 8);
            qf[1][d][3] = *(const unsigned*)(Ql + base1 + c0 + 8);
        }
    }

    float o[8][4];
    #pragma unroll
    for (int j = 0; j < 8; j++)
        #pragma unroll
        for (int e = 0; e < 4; e++) o[j][e] = 0.0f;
    float m0 = -1e30f, m1 = -1e30f, l0 = 0.0f, l1 = 0.0f;

    const int r_lo = q0 + 16 * w + (lane >> 2);
    const int r_hi = r_lo + 8;

    for (int kt = 0; kt <= ktmax; kt++) {
        cp_wait<1>();
        __syncthreads();

        const unsigned so = stage_off(kt);
        const int k0 = kt * 64;

        float s[8][4];
        #pragma unroll
        for (int j = 0; j < 8; j++)
            #pragma unroll
            for (int e = 0; e < 4; e++) s[j][e] = 0.0f;

        #pragma unroll
        for (int j = 0; j < 8; j++) {
            unsigned kbh[8], kbl[8];
            int krow = 8 * j + (lane & 7);
            int dct  = (lane >> 3) << 3;
            ldsm_x4(&kbh[0], sbase + (so + OKH + krow * RS + dct) * 2);
            ldsm_x4(&kbh[4], sbase + (so + OKH + krow * RS + 32 + dct) * 2);
            ldsm_x4(&kbl[0], sbase + (so + OKL + krow * RS + dct) * 2);
            ldsm_x4(&kbl[4], sbase + (so + OKL + krow * RS + 32 + dct) * 2);
            #pragma unroll
            for (int d = 0; d < 4; d++) {
                mma_bf16(s[j], qf[0][d], kbh[2*d], kbh[2*d+1]);
                mma_bf16(s[j], qf[0][d], kbl[2*d], kbl[2*d+1]);
                mma_bf16(s[j], qf[1][d], kbh[2*d], kbh[2*d+1]);
            }
        }

        if (masked && kt == qt) {
            #pragma unroll
            for (int j = 0; j < 8; j++) {
                int cc = k0 + 8 * j + 2 * (lane & 3);
                if (cc     > r_lo) s[j][0] = -1e30f;
                if (cc + 1 > r_lo) s[j][1] = -1e30f;
                if (cc     > r_hi) s[j][2] = -1e30f;
                if (cc + 1 > r_hi) s[j][3] = -1e30f;
            }
        }

        float mt0 = -1e30f, mt1 = -1e30f;
        #pragma unroll
        for (int j = 0; j < 8; j++) {
            mt0 = fmaxf(mt0, fmaxf(s[j][0], s[j][1]));
            mt1 = fmaxf(mt1, fmaxf(s[j][2], s[j][3]));
        }
        mt0 = fmaxf(mt0, __shfl_xor_sync(0xffffffffu, mt0, 1));
        mt0 = fmaxf(mt0, __shfl_xor_sync(0xffffffffu, mt0, 2));
        mt1 = fmaxf(mt1, __shfl_xor_sync(0xffffffffu, mt1, 1));
        mt1 = fmaxf(mt1, __shfl_xor_sync(0xffffffffu, mt1, 2));
        float mn0 = fmaxf(m0, mt0), mn1 = fmaxf(m1, mt1);
        float a0 = __expf(m0 - mn0), a1 = __expf(m1 - mn1);
        m0 = mn0; m1 = mn1;

        float rs0 = 0.0f, rs1 = 0.0f;
        unsigned pah[4][4], pal[4][4];
        #pragma unroll
        for (int j = 0; j < 8; j++) {
            float p0 = __expf(s[j][0] - mn0);
            float p1 = __expf(s[j][1] - mn0);
            float p2 = __expf(s[j][2] - mn1);
            float p3 = __expf(s[j][3] - mn1);
            rs0 += p0 + p1; rs1 += p2 + p3;
            unsigned h01 = packbf2(p1, p0);
            unsigned h23 = packbf2(p3, p2);
            float q0f = __uint_as_float(h01 << 16);
            float q1f = __uint_as_float(h01 & 0xffff0000u);
            float q2f = __uint_as_float(h23 << 16);
            float q3f = __uint_as_float(h23 & 0xffff0000u);
            unsigned lo01 = packbf2(p1 - q1f, p0 - q0f);
            unsigned lo23 = packbf2(p3 - q3f, p2 - q2f);
            int t = j >> 1, half = j & 1;
            pah[t][2 * half + 0] = h01;
            pah[t][2 * half + 1] = h23;
            pal[t][2 * half + 0] = lo01;
            pal[t][2 * half + 1] = lo23;
        }
        rs0 += __shfl_xor_sync(0xffffffffu, rs0, 1);
        rs0 += __shfl_xor_sync(0xffffffffu, rs0, 2);
        rs1 += __shfl_xor_sync(0xffffffffu, rs1, 1);
        rs1 += __shfl_xor_sync(0xffffffffu, rs1, 2);
        l0 = l0 * a0 + rs0;
        l1 = l1 * a1 + rs1;
        #pragma unroll
        for (int j = 0; j < 8; j++) {
            o[j][0] *= a0; o[j][1] *= a0;
            o[j][2] *= a1; o[j][3] *= a1;
        }

        #pragma unroll
        for (int jn = 0; jn < 8; jn++) {
            unsigned vbh[8], vbl[8];
            ldsm_x4_t(&vbh[0], sbase + (so + OVH + lane * RS + 8 * jn) * 2);
            ldsm_x4_t(&vbh[4], sbase + (so + OVH + (32 + lane) * RS + 8 * jn) * 2);
            ldsm_x4_t(&vbl[0], sbase + (so + OVL + lane * RS + 8 * jn) * 2);
            ldsm_x4_t(&vbl[4], sbase + (so + OVL + (32 + lane) * RS + 8 * jn) * 2);
            #pragma unroll
            for (int t = 0; t < 4; t++) {
                mma_bf16(o[jn], pah[t], vbh[2*t], vbh[2*t+1]);
                mma_bf16(o[jn], pah[t], vbl[2*t], vbl[2*t+1]);
                mma_bf16(o[jn], pal[t], vbh[2*t], vbh[2*t+1]);
            }
        }

        __syncthreads();
        prefetch(kt + 2);
    }

    float il0 = 1.0f / l0, il1 = 1.0f / l1;
    #pragma unroll
    for (int jn = 0; jn < 8; jn++) {
        int col = 8 * jn + 2 * (lane & 3);
        float f00 = o[jn][0] * il0, f01 = o[jn][1] * il0;
        float f10 = o[jn][2] * il1, f11 = o[jn][3] * il1;
        *(float2*)(merged + ((size_t)(b * SEQ + r_lo) * DIM) + h * HD + col) =
            make_float2(f00, f01);
        *(float2*)(merged + ((size_t)(b * SEQ + r_hi) * DIM) + h * HD + col) =
            make_float2(f10, f11);
        if (write_attn) {
            *(float2*)(attn_out + (((size_t)(b * NH + h) * SEQ + r_lo) * HD) + col) =
                make_float2(f00, f01);
            *(float2*)(attn_out + (((size_t)(b * NH + h) * SEQ + r_hi) * HD) + col) =
                make_float2(f10, f11);
        }
    }
}

// ---------------------------------------------------------------------------
extern "C" void kernel_launch(void* const* d_in, const int* in_sizes, int n_in,
                              void* d_out, int out_size)
{
    const float* q  = (const float*)d_in[0];
    const float* k  = (const float*)d_in[1];
    const float* v  = (const float*)d_in[2];
    const float* Wq = (const float*)d_in[3];
    const float* Wk = (const float*)d_in[4];
    const float* Wv = (const float*)d_in[5];
    const float* Wo = (const float*)d_in[6];
    const int* masked = (const int*)d_in[7];
    float* out = (float*)d_out;

    float* pM;
    __nv_bfloat16 *pQh, *pQl, *pKh, *pKl, *pVh, *pVl;
    cudaGetSymbolAddress((void**)&pM,  g_M);
    cudaGetSymbolAddress((void**)&pQh, g_Qh);
    cudaGetSymbolAddress((void**)&pQl, g_Ql);
    cudaGetSymbolAddress((void**)&pKh, g_Kh);
    cudaGetSymbolAddress((void**)&pKl, g_Kl);
    cudaGetSymbolAddress((void**)&pVh, g_Vh);
    cudaGetSymbolAddress((void**)&pVl, g_Vl);

    cudaFuncSetAttribute(qkv_gemm, cudaFuncAttributeMaxDynamicSharedMemorySize,
                         GEMM_SMEM);
    cudaFuncSetAttribute(wo_gemm, cudaFuncAttributeMaxDynamicSharedMemorySize,
                         GEMM_SMEM);

    // Fused Q/K/V projections: 64x128 tiles, 128-thread CTAs, 4 CTAs/SM
    dim3 gQKV(DIM / GBN, NTOK / GBM, 3);   // (8, 64, 3) = 1536 CTAs
    qkv_gemm<<<gQKV, 128, GEMM_SMEM>>>(q, k, v, Wq, Wk, Wv,
                                       pQh, pQl, pKh, pKl, pVh, pVl);

    // Attention (frozen R7 config)
    int write_attn = (out_size >= (int)(2 * NELEM)) ? 1 : 0;
    float* attn_ptr = out + NELEM;
    size_t fl_smem = (size_t)SB_TOTAL * sizeof(__nv_bfloat16);
    cudaFuncSetAttribute(flash_bf16, cudaFuncAttributeMaxDynamicSharedMemorySize,
                         (int)fl_smem);
    dim3 gAttn(SEQ / 64, NH, BSZ);         // (32, 16, 2)
    flash_bf16<<<gAttn, 128, fl_smem>>>(pQh, pQl, pKh, pKl, pVh, pVl,
                                        pM, attn_ptr, write_attn, masked);

    // Output projection
    dim3 gWo(DIM / GBN, NTOK / GBM);       // (8, 64)
    wo_gemm<<<gWo, 128, GEMM_SMEM>>>(pM, Wo, out);
}